// round 3
// baseline (speedup 1.0000x reference)
#include <cuda_runtime.h>
#include <cstdint>

// out[n,o] = (sum_k xq[n,k]*wq[o,k]) * sx*sw + bias[o]
// xq = round_half_even(x/sx) clamped [-128,127], sx = max|x|/127 (same for w).
// lut[i][j] == (i-128)*(j-128) -> gather is algebraically int8 multiply.
// N = IN = OUT = 512. Single persistent kernel: absmax -> quant -> IMMA GEMM.

#define NN 512
#define KK 512
#define OO 512

// ---- device scratch (no allocations allowed) ----
__device__ int g_maxx;             // float bits of max|x| (monotone under atomicMax)
__device__ int g_maxw;             // float bits of max|w|
__device__ unsigned g_ctr;         // monotonic grid-barrier counter (never reset)
__device__ int g_xa[NN * KK / 4];  // A fragments (m16n8k32): [rt16][kt32] x 32 lanes x 4 ints
__device__ int g_wb[OO * KK / 4];  // B fragments: [ct8][kt32] x 32 lanes x 2 ints

// ------------------------------------------------------------------
// fragment-layout address helpers (validated in round 2)
// A frag (row-major 16x32 s8): lane = (row%8)*4 + kw%4, j = row/8 + 2*(kw/4)
// B frag (col-major 32x8 s8):  lane = (col%8)*4 + kw%4, j = kw/4
// ------------------------------------------------------------------
__device__ __forceinline__ int xaddr(int r, int k0) {
    int rt = r >> 4, rr = r & 15, kt = k0 >> 5, kw = (k0 & 31) >> 2;
    int l = ((rr & 7) << 2) + (kw & 3);
    int j = (rr >> 3) + ((kw >> 2) << 1);
    return ((rt * 16 + kt) * 32 + l) * 4 + j;
}
__device__ __forceinline__ int waddr(int o, int k0) {
    int ct = o >> 3, cc = o & 7, kt = k0 >> 5, kw = (k0 & 31) >> 2;
    int l = (cc << 2) + (kw & 3);
    int j = kw >> 2;
    return ((ct * 16 + kt) * 32 + l) * 2 + j;
}

__device__ __forceinline__ int quant1(float v, float s) {
    int q = __float2int_rn(v / s);          // IEEE div + rn matches jnp.round
    q = max(-128, min(127, q));
    return q & 0xFF;
}
__device__ __forceinline__ int pack4(float4 v, float s) {
    return quant1(v.x, s) | (quant1(v.y, s) << 8) |
           (quant1(v.z, s) << 16) | (quant1(v.w, s) << 24);
}

__device__ __forceinline__ void mma_s8(int* c, const int4 a, const int2 b) {
    asm volatile(
        "mma.sync.aligned.m16n8k32.row.col.s32.s8.s8.s32 "
        "{%0,%1,%2,%3}, {%4,%5,%6,%7}, {%8,%9}, {%0,%1,%2,%3};"
        : "+r"(c[0]), "+r"(c[1]), "+r"(c[2]), "+r"(c[3])
        : "r"(a.x), "r"(a.y), "r"(a.z), "r"(a.w), "r"(b.x), "r"(b.y));
}

// Grid-wide barrier: monotonic counter, each barrier instance adds exactly
// 128 (one per block). Launch executes 2 barriers -> +256 per replay, always
// a multiple of 128, so target arithmetic is replay-safe with no reset.
__device__ __forceinline__ void grid_barrier(int tid) {
    __threadfence();
    __syncthreads();
    if (tid == 0) {
        unsigned arr = atomicAdd(&g_ctr, 1u) + 1u;
        unsigned target = ((arr + 127u) >> 7) << 7;   // ceil to multiple of 128
        while (*(volatile unsigned*)&g_ctr < target) { }
        __threadfence();
    }
    __syncthreads();
}

// ------------------------------------------------------------------
// One persistent kernel: 128 blocks x 256 threads, all co-resident.
//   Phase A: absmax of x and w (data held in registers)
//   Phase B: quantize from registers into fragment-ordered scratch
//   Phase C: IMMA GEMM, warp tile 16(M) x 16(N), 1024 warps total
// ------------------------------------------------------------------
__global__ __launch_bounds__(256, 1)
void fused_kernel(const float4* __restrict__ x, const float4* __restrict__ w,
                  const float* __restrict__ bias, float* __restrict__ out) {
    __shared__ float smx[8], smw[8];
    const int tid = threadIdx.x;
    const int t   = blockIdx.x * 256 + tid;        // 0..32767

    // ---------- Phase A: absmax ----------
    float4 xv0 = x[t], xv1 = x[t + 32768];
    float4 wv0 = w[t], wv1 = w[t + 32768];

    float mx = fmaxf(fmaxf(fmaxf(fabsf(xv0.x), fabsf(xv0.y)),
                           fmaxf(fabsf(xv0.z), fabsf(xv0.w))),
                     fmaxf(fmaxf(fabsf(xv1.x), fabsf(xv1.y)),
                           fmaxf(fabsf(xv1.z), fabsf(xv1.w))));
    float mw = fmaxf(fmaxf(fmaxf(fabsf(wv0.x), fabsf(wv0.y)),
                           fmaxf(fabsf(wv0.z), fabsf(wv0.w))),
                     fmaxf(fmaxf(fabsf(wv1.x), fabsf(wv1.y)),
                           fmaxf(fabsf(wv1.z), fabsf(wv1.w))));
    #pragma unroll
    for (int o = 16; o > 0; o >>= 1) {
        mx = fmaxf(mx, __shfl_xor_sync(0xFFFFFFFFu, mx, o));
        mw = fmaxf(mw, __shfl_xor_sync(0xFFFFFFFFu, mw, o));
    }
    if ((tid & 31) == 0) { smx[tid >> 5] = mx; smw[tid >> 5] = mw; }
    __syncthreads();
    if (tid == 0) {
        float bx = smx[0], bw = smw[0];
        #pragma unroll
        for (int i = 1; i < 8; ++i) { bx = fmaxf(bx, smx[i]); bw = fmaxf(bw, smw[i]); }
        atomicMax(&g_maxx, __float_as_int(bx));
        atomicMax(&g_maxw, __float_as_int(bw));
    }
    grid_barrier(tid);

    // ---------- Phase B: quantize from registers ----------
    const float sx = __int_as_float(*(volatile int*)&g_maxx) / 127.0f;
    const float sw = __int_as_float(*(volatile int*)&g_maxw) / 127.0f;
    {
        int i0 = t, i1 = t + 32768;
        int r0 = i0 >> 7, k0 = (i0 & 127) << 2;
        int r1 = i1 >> 7, k1 = (i1 & 127) << 2;
        g_xa[xaddr(r0, k0)] = pack4(xv0, sx);
        g_xa[xaddr(r1, k1)] = pack4(xv1, sx);
        g_wb[waddr(r0, k0)] = pack4(wv0, sw);
        g_wb[waddr(r1, k1)] = pack4(wv1, sw);
    }
    grid_barrier(tid);

    // ---------- Phase C: IMMA GEMM ----------
    // 1024 warps, each computes a 16x16 output tile (2 x m16n8k32 MMAs per kt).
    const int wid  = tid >> 5;
    const int lane = tid & 31;
    const int wt   = blockIdx.x * 8 + wid;   // 0..1023
    const int rt   = wt >> 5;                // 0..31  (16-row tile)
    const int ct0  = (wt & 31) << 1;         // 0..62  (two 8-col tiles)

    const int4* __restrict__ XA = (const int4*)g_xa;
    const int2* __restrict__ WB = (const int2*)g_wb;

    int acc[2][4];
    #pragma unroll
    for (int n = 0; n < 2; ++n)
        #pragma unroll
        for (int j = 0; j < 4; ++j) acc[n][j] = 0;

    #pragma unroll
    for (int kt = 0; kt < 16; ++kt) {
        int4 a  = XA[(rt * 16 + kt) * 32 + lane];
        int2 b0 = WB[((ct0 + 0) * 16 + kt) * 32 + lane];
        int2 b1 = WB[((ct0 + 1) * 16 + kt) * 32 + lane];
        mma_s8(acc[0], a, b0);
        mma_s8(acc[1], a, b1);
    }

    const float sc = sx * sw;
    const int g   = lane >> 2;       // row within tile
    const int tig = lane & 3;        // col pair within 8-col tile
    #pragma unroll
    for (int n = 0; n < 2; ++n) {
        int col = (ct0 + n) * 8 + tig * 2;
        float2 bb = *(const float2*)&bias[col];
        int row = rt * 16 + g;
        float2 v0 = { (float)acc[n][0] * sc + bb.x,
                      (float)acc[n][1] * sc + bb.y };
        float2 v1 = { (float)acc[n][2] * sc + bb.x,
                      (float)acc[n][3] * sc + bb.y };
        *(float2*)&out[row * OO + col]       = v0;
        *(float2*)&out[(row + 8) * OO + col] = v1;
    }
}

// ------------------------------------------------------------------
extern "C" void kernel_launch(void* const* d_in, const int* in_sizes, int n_in,
                              void* d_out, int out_size) {
    const float* x    = (const float*)d_in[0];   // [512,512]
    const float* w    = (const float*)d_in[1];   // [512,512]
    const float* bias = (const float*)d_in[2];   // [512]
    float* out = (float*)d_out;

    fused_kernel<<<128, 256>>>((const float4*)x, (const float4*)w, bias, out);
}